// round 2
// baseline (speedup 1.0000x reference)
#include <cuda_runtime.h>

#define BQ 4
#define NN 4096
#define DM 512
#define LP 4104   // padded length: ceil(4096/12)*12
#define NROWS (BQ*LP)

// ---------------- scratch (device globals; no allocation allowed) ----------------
__device__ float g_Y [BQ*NN*DM];   // conv output, (b*4096+t, d)
__device__ float g_Y2[BQ*LP*DM];   // pointwise output, (b*4104+l, d), pad rows zeroed
__device__ float g_T [NROWS];      // per-position score dot
__device__ float g_S [NROWS*4];    // softmaxed block scores
__device__ float g_S2[NROWS*4];    // attention-mixed scores

// ---------------- zero the 8 pad rows per batch of Y2 ----------------
__global__ void k_zero_pad() {
    int i = blockIdx.x * blockDim.x + threadIdx.x;  // 4*8*512 = 16384
    if (i < BQ * 8 * DM) {
        int b = i / (8 * DM);
        int r = i % (8 * DM);
        int l = NN + r / DM;
        int d = r % DM;
        g_Y2[((size_t)b * LP + l) * DM + d] = 0.0f;
    }
}

// ---------------- embedding gather + depthwise conv (K=4, causal-forward, zero pad at end) ----
__global__ void __launch_bounds__(128) k_conv(const int* __restrict__ x,
                                              const float* __restrict__ emb,
                                              const float* __restrict__ dww,
                                              const float* __restrict__ dwb) {
    int t = blockIdx.x;
    int b = blockIdx.y;
    int d0 = threadIdx.x * 4;

    // weights: dww[d*4 + k]
    float w[4][4];
#pragma unroll
    for (int j = 0; j < 4; j++) {
        float4 wv = *(const float4*)(dww + (d0 + j) * 4);
        w[j][0] = wv.x; w[j][1] = wv.y; w[j][2] = wv.z; w[j][3] = wv.w;
    }
    float4 bb = *(const float4*)(dwb + d0);
    float acc[4] = {bb.x, bb.y, bb.z, bb.w};

#pragma unroll
    for (int k = 0; k < 4; k++) {
        int tt = t + k;
        if (tt < NN) {
            int id = x[b * NN + tt];
            float4 e = *(const float4*)(emb + (size_t)id * DM + d0);
            acc[0] += e.x * w[0][k];
            acc[1] += e.y * w[1][k];
            acc[2] += e.z * w[2][k];
            acc[3] += e.w * w[3][k];
        }
    }
    float4 o = {acc[0], acc[1], acc[2], acc[3]};
    *(float4*)(g_Y + ((size_t)(b * NN + t)) * DM + d0) = o;
}

// ---------------- pointwise GEMM: Y2[row, e] = sum_d Y[row, d] * W[e, d] + bias[e] ----------
// NT GEMM: A (16384 x 512) row-major, B = pw_w (512 x 512) row-major (both K-contiguous)
#define BMT 64
#define BNT 64
#define BKT 16
__global__ void __launch_bounds__(256) k_gemm(const float* __restrict__ W,
                                              const float* __restrict__ bias) {
    __shared__ float As[BKT][BMT];
    __shared__ float Bs[BKT][BNT];

    int bn = blockIdx.x;   // 0..7
    int bm = blockIdx.y;   // 0..255
    int tid = threadIdx.x;
    int tx = tid & 15;     // n sub
    int ty = tid >> 4;     // m sub

    const float* A  = g_Y + (size_t)bm * BMT * DM;
    const float* Bp = W   + (size_t)bn * BNT * DM;

    int lr = tid >> 2;          // load row 0..63
    int lk = (tid & 3) * 4;     // load k offset 0,4,8,12

    float acc[4][4];
#pragma unroll
    for (int i = 0; i < 4; i++)
#pragma unroll
        for (int j = 0; j < 4; j++) acc[i][j] = 0.0f;

    for (int kt = 0; kt < DM; kt += BKT) {
        float4 a4 = *(const float4*)(A  + (size_t)lr * DM + kt + lk);
        float4 b4 = *(const float4*)(Bp + (size_t)lr * DM + kt + lk);
        As[lk + 0][lr] = a4.x; As[lk + 1][lr] = a4.y;
        As[lk + 2][lr] = a4.z; As[lk + 3][lr] = a4.w;
        Bs[lk + 0][lr] = b4.x; Bs[lk + 1][lr] = b4.y;
        Bs[lk + 2][lr] = b4.z; Bs[lk + 3][lr] = b4.w;
        __syncthreads();
#pragma unroll
        for (int kk = 0; kk < BKT; kk++) {
            float4 av = *(const float4*)(&As[kk][ty * 4]);
            float4 bv = *(const float4*)(&Bs[kk][tx * 4]);
            float a[4] = {av.x, av.y, av.z, av.w};
            float b[4] = {bv.x, bv.y, bv.z, bv.w};
#pragma unroll
            for (int i = 0; i < 4; i++)
#pragma unroll
                for (int j = 0; j < 4; j++) acc[i][j] += a[i] * b[j];
        }
        __syncthreads();
    }

    int col = bn * BNT + tx * 4;
    float4 bias4 = *(const float4*)(bias + col);
#pragma unroll
    for (int i = 0; i < 4; i++) {
        int r = bm * BMT + ty * 4 + i;
        int b = r >> 12;          // row / 4096
        int l = r & 4095;
        float4 o = {acc[i][0] + bias4.x, acc[i][1] + bias4.y,
                    acc[i][2] + bias4.z, acc[i][3] + bias4.w};
        *(float4*)(g_Y2 + ((size_t)b * LP + l) * DM + col) = o;
    }
}

// ---------------- per-position score dot: T[row] = dot(Y2[row], score_w) -------------
__global__ void __launch_bounds__(256) k_tdot(const float* __restrict__ sw) {
    int warp = (blockIdx.x * blockDim.x + threadIdx.x) >> 5;
    int lane = threadIdx.x & 31;
    if (warp >= NROWS) return;
    const float4* row = (const float4*)(g_Y2 + (size_t)warp * DM);
    const float4* swv = (const float4*)sw;
    float s = 0.0f;
#pragma unroll
    for (int q = 0; q < 4; q++) {
        float4 v = row[lane + q * 32];
        float4 w = swv[lane + q * 32];
        s += v.x * w.x + v.y * w.y + v.z * w.z + v.w * w.w;
    }
#pragma unroll
    for (int o = 16; o; o >>= 1) s += __shfl_xor_sync(0xffffffff, s, o);
    if (lane == 0) g_T[warp] = s;
}

// ---------------- block means of T + softmax over k (4 block sizes) -----------------
__global__ void __launch_bounds__(256) k_scores(const float* __restrict__ sb) {
    int idx = blockIdx.x * blockDim.x + threadIdx.x;
    if (idx >= NROWS) return;
    int b = idx / LP, l = idx % LP;
    const float* Tb = g_T + (size_t)b * LP;
    float v[4];
    v[0] = Tb[l];
    { int j = l & ~1;      v[1] = (Tb[j] + Tb[j + 1]) * 0.5f; }
    { int j = (l / 3) * 3; v[2] = (Tb[j] + Tb[j + 1] + Tb[j + 2]) * (1.0f / 3.0f); }
    { int j = l & ~3;      v[3] = (Tb[j] + Tb[j + 1] + Tb[j + 2] + Tb[j + 3]) * 0.25f; }
    float bb = sb[0];
    float mx = v[0];
#pragma unroll
    for (int k = 1; k < 4; k++) mx = fmaxf(mx, v[k]);
    float e[4], z = 0.0f;
#pragma unroll
    for (int k = 0; k < 4; k++) { e[k] = __expf(v[k] + bb - (mx + bb)); z += e[k]; }
    float inv = 1.0f / z;
    float4 o = {e[0] * inv, e[1] * inv, e[2] * inv, e[3] * inv};
    *(float4*)(g_S + (size_t)idx * 4) = o;
}

// ---------------- score attention: S2_i = sum_j exp(s_i . s_j) s_j / Z_i ------------
__global__ void __launch_bounds__(256) k_attn() {
    extern __shared__ float4 sS[];   // 4104 entries = 65664 B
    int b = blockIdx.y;
    const float4* Sb = (const float4*)(g_S + (size_t)b * LP * 4);
    for (int j = threadIdx.x; j < LP; j += 256) sS[j] = Sb[j];
    __syncthreads();

    int i = blockIdx.x * 256 + threadIdx.x;
    if (i >= LP) return;
    float4 q = sS[i];
    float z = 0.0f, a0 = 0.0f, a1 = 0.0f, a2 = 0.0f, a3 = 0.0f;
#pragma unroll 4
    for (int j = 0; j < LP; j++) {
        float4 s = sS[j];
        float d = q.x * s.x + q.y * s.y + q.z * s.z + q.w * s.w;
        float e = __expf(d);
        z  += e;
        a0 += e * s.x; a1 += e * s.y; a2 += e * s.z; a3 += e * s.w;
    }
    float inv = 1.0f / z;
    float4 r = {a0 * inv, a1 * inv, a2 * inv, a3 * inv};
    *(float4*)(g_S2 + ((size_t)b * LP + i) * 4) = r;
}

// ---------------- output: weighted pooling of Y2 rows over block windows + DS mean ----
__global__ void __launch_bounds__(128) k_out(float* __restrict__ out) {
    int g = blockIdx.x;    // 0..1023
    int b = blockIdx.y;
    int base = 4 * g - 2;  // window [4g-2, 4g+5], 8 slots

    float w[8];
#pragma unroll
    for (int r = 0; r < 8; r++) w[r] = 0.0f;

#pragma unroll
    for (int lo = 0; lo < 4; lo++) {
        int l = 4 * g + lo;
        const float4 s2 = *(const float4*)(g_S2 + ((size_t)b * LP + l) * 4);
        // bs = 1
        w[l - base] += s2.x * 0.25f;
        // bs = 2
        {
            int j0 = l & ~1; float c = s2.y * (0.25f * 0.5f);
            w[j0 - base] += c; w[j0 + 1 - base] += c;
        }
        // bs = 3
        {
            int j0 = (l / 3) * 3; float c = s2.z * (0.25f / 3.0f);
            w[j0 - base] += c; w[j0 + 1 - base] += c; w[j0 + 2 - base] += c;
        }
        // bs = 4
        {
            int j0 = l & ~3; float c = s2.w * (0.25f * 0.25f);
            w[j0 - base] += c; w[j0 + 1 - base] += c;
            w[j0 + 2 - base] += c; w[j0 + 3 - base] += c;
        }
    }

    int d = threadIdx.x * 4;  // 128 threads x float4 covers 512
    float4 acc = {0.0f, 0.0f, 0.0f, 0.0f};
#pragma unroll
    for (int r = 0; r < 8; r++) {
        int row = base + r;
        float wr = w[r];
        if (row >= 0 && wr != 0.0f) {
            float4 v = *(const float4*)(g_Y2 + ((size_t)b * LP + row) * DM + d);
            acc.x += wr * v.x; acc.y += wr * v.y;
            acc.z += wr * v.z; acc.w += wr * v.w;
        }
    }
    *(float4*)(out + ((size_t)(b * 1024 + g)) * DM + d) = acc;
}

// ---------------- launcher ----------------
extern "C" void kernel_launch(void* const* d_in, const int* in_sizes, int n_in,
                              void* d_out, int out_size) {
    const int*   x   = (const int*)  d_in[0];
    const float* emb = (const float*)d_in[1];
    const float* dww = (const float*)d_in[2];
    const float* dwb = (const float*)d_in[3];
    const float* pww = (const float*)d_in[4];
    const float* pwb = (const float*)d_in[5];
    const float* sw  = (const float*)d_in[6];
    const float* sb  = (const float*)d_in[7];
    float* out = (float*)d_out;

    cudaFuncSetAttribute(k_attn, cudaFuncAttributeMaxDynamicSharedMemorySize, LP * 16);

    k_zero_pad<<<(BQ * 8 * DM + 255) / 256, 256>>>();
    k_conv<<<dim3(NN, BQ), 128>>>(x, emb, dww, dwb);
    k_gemm<<<dim3(DM / BNT, (BQ * NN) / BMT), 256>>>(pww, pwb);
    k_tdot<<<(NROWS * 32 + 255) / 256, 256>>>(sw);
    k_scores<<<(NROWS + 255) / 256, 256>>>(sb);
    k_attn<<<dim3((LP + 255) / 256, BQ), 256, LP * 16>>>();
    k_out<<<dim3(1024, BQ), 128>>>(out);
}

// round 4
// speedup vs baseline: 3.0771x; 3.0771x over previous
#include <cuda_runtime.h>
#include <cuda_bf16.h>
#include <cstdint>

#define BQ 4
#define NN 4096
#define DM 512
#define LP 4104   // ceil(4096/12)*12
#define NROWS (BQ*LP)

// ---------------- scratch (device globals) ----------------
__device__ __nv_bfloat16 g_Yh[(size_t)BQ*NN*DM];   // conv output hi
__device__ __nv_bfloat16 g_Yl[(size_t)BQ*NN*DM];   // conv output lo
__device__ __nv_bfloat16 g_Wh[DM*DM];              // pw_w hi
__device__ __nv_bfloat16 g_Wl[DM*DM];              // pw_w lo
__device__ float g_Y2[(size_t)BQ*LP*DM];           // pointwise output
__device__ float g_T [NROWS];                      // per-position score dot (atomic)
__device__ float g_S [NROWS*4];                    // softmaxed block scores
__device__ float g_S2[NROWS*4];                    // attention-mixed scores

// ---------------- zero pad rows of Y2 + zero g_T ----------------
__global__ void k_zero_pad() {
    int i = blockIdx.x * blockDim.x + threadIdx.x;
    if (i < NROWS) g_T[i] = 0.0f;
    if (i < BQ * 8 * DM) {
        int b = i / (8 * DM);
        int r = i % (8 * DM);
        int l = NN + r / DM;
        int d = r % DM;
        g_Y2[((size_t)b * LP + l) * DM + d] = 0.0f;
    }
}

// ---------------- split pw_w into bf16 hi/lo ----------------
__global__ void k_wsplit(const float* __restrict__ W) {
    int i = blockIdx.x * blockDim.x + threadIdx.x;
    if (i < DM * DM) {
        float w = W[i];
        __nv_bfloat16 h = __float2bfloat16(w);
        g_Wh[i] = h;
        g_Wl[i] = __float2bfloat16(w - __bfloat162float(h));
    }
}

// ---------------- embedding gather + depthwise conv, output bf16 hi/lo ----------------
__global__ void __launch_bounds__(128) k_conv(const int* __restrict__ x,
                                              const float* __restrict__ emb,
                                              const float* __restrict__ dww,
                                              const float* __restrict__ dwb) {
    int t = blockIdx.x;
    int b = blockIdx.y;
    int d0 = threadIdx.x * 4;

    float w[4][4];
#pragma unroll
    for (int j = 0; j < 4; j++) {
        float4 wv = *(const float4*)(dww + (d0 + j) * 4);
        w[j][0] = wv.x; w[j][1] = wv.y; w[j][2] = wv.z; w[j][3] = wv.w;
    }
    float4 bb = *(const float4*)(dwb + d0);
    float acc[4] = {bb.x, bb.y, bb.z, bb.w};

#pragma unroll
    for (int k = 0; k < 4; k++) {
        int tt = t + k;
        if (tt < NN) {
            int id = x[b * NN + tt];
            float4 e = *(const float4*)(emb + (size_t)id * DM + d0);
            acc[0] += e.x * w[0][k];
            acc[1] += e.y * w[1][k];
            acc[2] += e.z * w[2][k];
            acc[3] += e.w * w[3][k];
        }
    }
    size_t base = ((size_t)(b * NN + t)) * DM + d0;
    __nv_bfloat16 h[4], l[4];
#pragma unroll
    for (int j = 0; j < 4; j++) {
        h[j] = __float2bfloat16(acc[j]);
        l[j] = __float2bfloat16(acc[j] - __bfloat162float(h[j]));
    }
    __nv_bfloat162* ph = (__nv_bfloat162*)(g_Yh + base);
    __nv_bfloat162* pl = (__nv_bfloat162*)(g_Yl + base);
    ph[0] = __halves2bfloat162(h[0], h[1]);
    ph[1] = __halves2bfloat162(h[2], h[3]);
    pl[0] = __halves2bfloat162(l[0], l[1]);
    pl[1] = __halves2bfloat162(l[2], l[3]);
}

// ---------------- HMMA GEMM: Y2 = Y @ W^T + bias, bf16x3 split precision ----------------
// grid (128 mtiles, 4 ntiles). CTA tile 128x128, BK=32, 8 warps (2m x 4n), warp 64x32.
#define SST 80            // smem row stride in bytes (20 u32 -> conflict-free ldmatrix)
#define TILE_B (128*SST)  // 10240

__device__ __forceinline__ void ldsm4(uint32_t* r, uint32_t addr) {
    asm volatile("ldmatrix.sync.aligned.m8n8.x4.shared.b16 {%0,%1,%2,%3}, [%4];"
                 : "=r"(r[0]), "=r"(r[1]), "=r"(r[2]), "=r"(r[3]) : "r"(addr));
}
__device__ __forceinline__ void mma16816(float* c, const uint32_t* a, const uint32_t* b) {
    asm volatile(
        "mma.sync.aligned.m16n8k16.row.col.f32.bf16.bf16.f32 "
        "{%0,%1,%2,%3}, {%4,%5,%6,%7}, {%8,%9}, {%0,%1,%2,%3};"
        : "+f"(c[0]), "+f"(c[1]), "+f"(c[2]), "+f"(c[3])
        : "r"(a[0]), "r"(a[1]), "r"(a[2]), "r"(a[3]), "r"(b[0]), "r"(b[1]));
}

__global__ void __launch_bounds__(256, 2) k_gemm_mma(const float* __restrict__ bias,
                                                     const float* __restrict__ sw) {
    __shared__ char sm[4 * TILE_B];
    char* sAh = sm;
    char* sAl = sm + TILE_B;
    char* sBh = sm + 2 * TILE_B;
    char* sBl = sm + 3 * TILE_B;

    int tid = threadIdx.x, wid = tid >> 5, lane = tid & 31;
    int warp_m = wid & 1;       // 0..1 -> 64 rows each
    int warp_n = wid >> 1;      // 0..3 -> 32 cols each
    int mtile = blockIdx.x;     // 0..127
    int bn = blockIdx.y;        // 0..3

    const __nv_bfloat16* gAh = g_Yh + (size_t)mtile * 128 * DM;
    const __nv_bfloat16* gAl = g_Yl + (size_t)mtile * 128 * DM;
    const __nv_bfloat16* gBh = g_Wh + (size_t)bn * 128 * DM;
    const __nv_bfloat16* gBl = g_Wl + (size_t)bn * 128 * DM;

    float c[4][4][4];
#pragma unroll
    for (int mt = 0; mt < 4; mt++)
#pragma unroll
        for (int nt = 0; nt < 4; nt++)
#pragma unroll
            for (int e = 0; e < 4; e++) c[mt][nt][e] = 0.0f;

    // ldmatrix lane address components
    int lr = lane & 7, g = lane >> 3;
    int a_row = (g & 1) * 8 + lr;        // row within m16 tile
    int a_kh  = (g >> 1) * 8;            // k half (0|8)
    int b_nrw = (g >> 1) * 8 + lr;       // n row within n16 group
    int b_kh  = (g & 1) * 8;             // k half (0|8)

    uint32_t sAh_u = (uint32_t)__cvta_generic_to_shared(sAh);
    uint32_t sAl_u = (uint32_t)__cvta_generic_to_shared(sAl);
    uint32_t sBh_u = (uint32_t)__cvta_generic_to_shared(sBh);
    uint32_t sBl_u = (uint32_t)__cvta_generic_to_shared(sBl);

    for (int kc = 0; kc < 16; kc++) {
        if (kc) __syncthreads();
        // load 4 tiles: each thread 2 uint4 per tile (512 uint4/tile)
#pragma unroll
        for (int h = 0; h < 2; h++) {
            int v = tid + h * 256;
            int r = v >> 2, cc = v & 3;
            size_t go = (size_t)r * DM + kc * 32 + cc * 8;
            uint32_t so = r * SST + cc * 16;
            *(uint4*)(sAh + so) = *(const uint4*)(gAh + go);
            *(uint4*)(sAl + so) = *(const uint4*)(gAl + go);
            *(uint4*)(sBh + so) = *(const uint4*)(gBh + go);
            *(uint4*)(sBl + so) = *(const uint4*)(gBl + go);
        }
        __syncthreads();

#pragma unroll
        for (int pass = 0; pass < 3; pass++) {
            uint32_t As = (pass == 2) ? sAl_u : sAh_u;
            uint32_t Bs = (pass == 1) ? sBl_u : sBh_u;
#pragma unroll
            for (int ks = 0; ks < 2; ks++) {
                uint32_t a[4][4];
#pragma unroll
                for (int mt = 0; mt < 4; mt++) {
                    uint32_t ad = As + (uint32_t)((warp_m * 64 + mt * 16 + a_row) * SST
                                                  + (ks * 16 + a_kh) * 2);
                    ldsm4(a[mt], ad);
                }
                uint32_t b[8];
#pragma unroll
                for (int hh = 0; hh < 2; hh++) {
                    uint32_t bd = Bs + (uint32_t)((warp_n * 32 + hh * 16 + b_nrw) * SST
                                                  + (ks * 16 + b_kh) * 2);
                    ldsm4(b + hh * 4, bd);
                }
#pragma unroll
                for (int mt = 0; mt < 4; mt++)
#pragma unroll
                    for (int nt = 0; nt < 4; nt++) {
                        uint32_t bb[2] = {b[(nt >> 1) * 4 + (nt & 1) * 2],
                                          b[(nt >> 1) * 4 + (nt & 1) * 2 + 1]};
                        mma16816(c[mt][nt], a[mt], bb);
                    }
            }
        }
    }

    // epilogue: bias add + fused tdot + store
    float tp[4][2];
#pragma unroll
    for (int mt = 0; mt < 4; mt++) { tp[mt][0] = 0.0f; tp[mt][1] = 0.0f; }

#pragma unroll
    for (int mt = 0; mt < 4; mt++) {
        int row0 = mtile * 128 + warp_m * 64 + mt * 16 + (lane >> 2);
        int row1 = row0 + 8;
        int b0i = row0 >> 12, l0i = row0 & 4095;
        int b1i = row1 >> 12, l1i = row1 & 4095;
        float* o0 = g_Y2 + ((size_t)b0i * LP + l0i) * DM;
        float* o1 = g_Y2 + ((size_t)b1i * LP + l1i) * DM;
#pragma unroll
        for (int nt = 0; nt < 4; nt++) {
            int col = bn * 128 + warp_n * 32 + nt * 8 + 2 * (lane & 3);
            float bi0 = bias[col], bi1 = bias[col + 1];
            float s0 = sw[col], s1 = sw[col + 1];
            float v00 = c[mt][nt][0] + bi0, v01 = c[mt][nt][1] + bi1;
            float v10 = c[mt][nt][2] + bi0, v11 = c[mt][nt][3] + bi1;
            tp[mt][0] += v00 * s0 + v01 * s1;
            tp[mt][1] += v10 * s0 + v11 * s1;
            float2 w0 = {v00, v01}, w1 = {v10, v11};
            *(float2*)(o0 + col) = w0;
            *(float2*)(o1 + col) = w1;
        }
    }
    // reduce tdot partials over the 4 lanes sharing a row
#pragma unroll
    for (int mt = 0; mt < 4; mt++) {
#pragma unroll
        for (int rs = 0; rs < 2; rs++) {
            float r = tp[mt][rs];
            r += __shfl_xor_sync(0xffffffff, r, 1);
            r += __shfl_xor_sync(0xffffffff, r, 2);
            if ((lane & 3) == 0) {
                int row = mtile * 128 + warp_m * 64 + mt * 16 + rs * 8 + (lane >> 2);
                int bb = row >> 12, ll = row & 4095;
                atomicAdd(&g_T[bb * LP + ll], r);
            }
        }
    }
}

// ---------------- block means of T + softmax over k ----------------
__global__ void __launch_bounds__(256) k_scores(const float* __restrict__ sb) {
    int idx = blockIdx.x * blockDim.x + threadIdx.x;
    if (idx >= NROWS) return;
    int b = idx / LP, l = idx % LP;
    const float* Tb = g_T + (size_t)b * LP;
    float v[4];
    v[0] = Tb[l];
    { int j = l & ~1;      v[1] = (Tb[j] + Tb[j + 1]) * 0.5f; }
    { int j = (l / 3) * 3; v[2] = (Tb[j] + Tb[j + 1] + Tb[j + 2]) * (1.0f / 3.0f); }
    { int j = l & ~3;      v[3] = (Tb[j] + Tb[j + 1] + Tb[j + 2] + Tb[j + 3]) * 0.25f; }
    float mx = v[0];
#pragma unroll
    for (int k = 1; k < 4; k++) mx = fmaxf(mx, v[k]);
    float e[4], z = 0.0f;
#pragma unroll
    for (int k = 0; k < 4; k++) { e[k] = __expf(v[k] - mx); z += e[k]; }
    float inv = 1.0f / z;
    float4 o = {e[0] * inv, e[1] * inv, e[2] * inv, e[3] * inv};
    *(float4*)(g_S + (size_t)idx * 4) = o;
}

// ---------------- score attention ----------------
__global__ void __launch_bounds__(128) k_attn() {
    extern __shared__ float4 sS[];   // LP entries
    int b = blockIdx.y;
    const float4* Sb = (const float4*)(g_S + (size_t)b * LP * 4);
    for (int j = threadIdx.x; j < LP; j += 128) sS[j] = Sb[j];
    __syncthreads();

    int i = blockIdx.x * 128 + threadIdx.x;
    if (i >= LP) return;
    float4 q = sS[i];
    const float L2E = 1.4426950408889634f;
    float qx = q.x * L2E, qy = q.y * L2E, qz = q.z * L2E, qw = q.w * L2E;
    float z = 0.0f, a0 = 0.0f, a1 = 0.0f, a2 = 0.0f, a3 = 0.0f;
#pragma unroll 8
    for (int j = 0; j < LP; j++) {
        float4 s = sS[j];
        float d = fmaf(qx, s.x, fmaf(qy, s.y, fmaf(qz, s.z, qw * s.w)));
        float e;
        asm("ex2.approx.f32 %0, %1;" : "=f"(e) : "f"(d));
        z += e;
        a0 = fmaf(e, s.x, a0); a1 = fmaf(e, s.y, a1);
        a2 = fmaf(e, s.z, a2); a3 = fmaf(e, s.w, a3);
    }
    float inv = 1.0f / z;
    float4 r = {a0 * inv, a1 * inv, a2 * inv, a3 * inv};
    *(float4*)(g_S2 + ((size_t)b * LP + i) * 4) = r;
}

// ---------------- output: weighted pooling + DS mean ----------------
__global__ void __launch_bounds__(128) k_out(float* __restrict__ out) {
    int g = blockIdx.x;
    int b = blockIdx.y;
    int base = 4 * g - 2;

    float w[8];
#pragma unroll
    for (int r = 0; r < 8; r++) w[r] = 0.0f;

#pragma unroll
    for (int lo = 0; lo < 4; lo++) {
        int l = 4 * g + lo;
        const float4 s2 = *(const float4*)(g_S2 + ((size_t)b * LP + l) * 4);
        w[l - base] += s2.x * 0.25f;
        { int j0 = l & ~1;      float c = s2.y * (0.25f * 0.5f);
          w[j0 - base] += c; w[j0 + 1 - base] += c; }
        { int j0 = (l / 3) * 3; float c = s2.z * (0.25f / 3.0f);
          w[j0 - base] += c; w[j0 + 1 - base] += c; w[j0 + 2 - base] += c; }
        { int j0 = l & ~3;      float c = s2.w * (0.25f * 0.25f);
          w[j0 - base] += c; w[j0 + 1 - base] += c;
          w[j0 + 2 - base] += c; w[j0 + 3 - base] += c; }
    }

    int d = threadIdx.x * 4;
    float4 acc = {0.0f, 0.0f, 0.0f, 0.0f};
#pragma unroll
    for (int r = 0; r < 8; r++) {
        int row = base + r;
        float wr = w[r];
        if (row >= 0 && wr != 0.0f) {
            float4 v = *(const float4*)(g_Y2 + ((size_t)b * LP + row) * DM + d);
            acc.x += wr * v.x; acc.y += wr * v.y;
            acc.z += wr * v.z; acc.w += wr * v.w;
        }
    }
    *(float4*)(out + ((size_t)(b * 1024 + g)) * DM + d) = acc;
}

// ---------------- launcher ----------------
extern "C" void kernel_launch(void* const* d_in, const int* in_sizes, int n_in,
                              void* d_out, int out_size) {
    const int*   x   = (const int*)  d_in[0];
    const float* emb = (const float*)d_in[1];
    const float* dww = (const float*)d_in[2];
    const float* dwb = (const float*)d_in[3];
    const float* pww = (const float*)d_in[4];
    const float* pwb = (const float*)d_in[5];
    const float* sw  = (const float*)d_in[6];
    const float* sb  = (const float*)d_in[7];
    float* out = (float*)d_out;

    cudaFuncSetAttribute(k_attn, cudaFuncAttributeMaxDynamicSharedMemorySize, LP * 16);

    k_zero_pad<<<(NROWS + 255) / 256, 256>>>();
    k_wsplit<<<(DM * DM + 255) / 256, 256>>>(pww);
    k_conv<<<dim3(NN, BQ), 128>>>(x, emb, dww, dwb);
    k_gemm_mma<<<dim3(128, 4), 256>>>(pwb, sw);
    k_scores<<<(NROWS + 255) / 256, 256>>>(sb);
    k_attn<<<dim3((LP + 127) / 128, BQ), 128, LP * 16>>>();
    k_out<<<dim3(1024, BQ), 128>>>(out);
}